// round 7
// baseline (speedup 1.0000x reference)
#include <cuda_runtime.h>

#define T_HOR 100
#define B_BATCH 512
#define REGU 1e-6f

typedef unsigned long long ull;

__device__ float g_K[B_BATCH * T_HOR * 8 * 24];
__device__ float g_kv[B_BATCH * T_HOR * 8];

__device__ __forceinline__ ull pack2(float s) {
    ull d; asm("mov.b64 %0, {%1, %1};" : "=l"(d) : "f"(s)); return d;
}
__device__ __forceinline__ void ffma2(ull& d, ull a, ull b) {
    asm("fma.rn.f32x2 %0, %1, %2, %0;" : "+l"(d) : "l"(a), "l"(b));
}
__device__ __forceinline__ float2 unpack2(ull v) {
    float2 r; asm("mov.b64 {%0, %1}, %2;" : "=f"(r.x), "=f"(r.y) : "l"(v)); return r;
}

extern "C" __global__ void __launch_bounds__(128, 4)
lqr_kernel(const float* __restrict__ d_x0,
           const float* __restrict__ d_C,
           const float* __restrict__ d_c,
           const float* __restrict__ d_Cf,
           const float* __restrict__ d_cf,
           const float* __restrict__ d_xref,
           const float* __restrict__ d_uref,
           const float* __restrict__ d_A,
           const float* __restrict__ d_B,
           float* __restrict__ d_out)
{
    __shared__ __align__(16) float sAB[24 * 36];
    __shared__ __align__(16) float sV[24 * 28];
    __shared__ __align__(16) float sC[32 * 36];
    __shared__ __align__(16) float sG[24 * 36];
    __shared__ __align__(16) float sH[32 * 36];
    __shared__ __align__(16) float sK[8 * 28];
    __shared__ __align__(16) float sK2[192];
    __shared__ __align__(16) float sQ[32], sc2[32], szref[32], sv[32];
    __shared__ float skv[8], su[8];
    __shared__ float sx[2][24];

    const int tid = threadIdx.x;
    const int b = blockIdx.x;

    // triangle tile maps
    int e_ti = 0, e_tk = 0;      // stage E: tid>>1 over 21 lower tiles (6x6)
    {
        const int tt = tid >> 1;
        int s = 0;
        #pragma unroll
        for (int i = 0; i < 6; i++) {
            if (tt >= s && tt < s + i + 1) { e_ti = i; e_tk = tt - s; }
            s += i + 1;
        }
    }
    int b_bi = 0, b_bk = 0;      // stage B: tid over 36 lower tiles (8x8), 1 thr/tile
    {
        int s = 0;
        #pragma unroll
        for (int i = 0; i < 8; i++) {
            if (tid >= s && tid < s + i + 1) { b_bi = i; b_bk = tid - s; }
            s += i + 1;
        }
    }

    // ---------------- preamble ----------------
    for (int e = tid; e < 24 * 32; e += 128) {
        int j = e >> 5, cc = e & 31;
        sAB[j * 36 + cc] = (cc < 24) ? d_A[j * 24 + cc] : d_B[j * 8 + (cc - 24)];
    }
    for (int e = tid; e < 576; e += 128) {
        int i = e / 24, j = e - i * 24;
        sV[i * 28 + j] = d_Cf[(size_t)b * 1024 + i * 32 + j];
    }
    if (tid < 24) sQ[tid] = d_xref[((size_t)b * 101 + 100) * 24 + tid];
    {
        const float4* C4 = (const float4*)(d_C + ((size_t)b * T_HOR + 99) * 1024);
        #pragma unroll
        for (int ss = 0; ss < 2; ss++) {
            const int s = tid + ss * 128;
            *(float4*)(sC + (s >> 3) * 36 + ((s & 7) << 2)) = C4[s];
        }
        if (tid < 32)
            sc2[tid] = d_c[((size_t)b * T_HOR + 99) * 32 + tid];
        else if (tid < 56)
            szref[tid - 32] = d_xref[((size_t)b * 101 + 99) * 24 + (tid - 32)];
        else if (tid < 64)
            szref[24 + tid - 56] = d_uref[((size_t)b * T_HOR + 99) * 8 + (tid - 56)];
    }
    __syncthreads();
    if (tid < 24) {
        float acc = d_cf[b * 32 + tid];
        #pragma unroll
        for (int j = 0; j < 24; j++) acc -= sV[tid * 28 + j] * sQ[j];
        sv[tid] = acc;
    }
    __syncthreads();

    // ---------------- backward Riccati ----------------
    for (int t = 99; t >= 0; --t) {
        // prefetch t-1 (threads 32..127)
        float4 pc0 = make_float4(0.f,0.f,0.f,0.f), pc1 = pc0, pc2 = pc0;
        float psc = 0.f;
        if (t > 0 && tid >= 32) {
            const float4* C4 = (const float4*)(d_C + ((size_t)b * T_HOR + t - 1) * 1024);
            const int idx = tid - 32;
            pc0 = C4[idx];
            pc1 = C4[idx + 96];
            if (tid < 96) pc2 = C4[idx + 192];
            if (tid < 64)
                psc = d_c[((size_t)b * T_HOR + t - 1) * 32 + (tid - 32)];
            else if (tid < 88)
                psc = d_xref[((size_t)b * 101 + t - 1) * 24 + (tid - 64)];
            else if (tid < 96)
                psc = d_uref[((size_t)b * T_HOR + t - 1) * 8 + (tid - 88)];
        }

        // ---- stage A: G = V*[A|B] (48 thr, 4x4, f32x2) ; Q = [Qx|Qu] (32 thr)
        if (tid < 48) {
            const int i0 = (tid >> 3) * 4, c4 = (tid & 7) << 2;
            ull aL[4], aH[4];
            #pragma unroll
            for (int r = 0; r < 4; r++) { aL[r] = 0; aH[r] = 0; }
            #pragma unroll
            for (int j = 0; j < 24; j++) {
                const float4 vv = *(const float4*)(sV + j * 28 + i0);   // V[i0..i0+3][j] (sym)
                const ulonglong2 ab = *(const ulonglong2*)(sAB + j * 36 + c4);
                #pragma unroll
                for (int r = 0; r < 4; r++) {
                    const ull vr = pack2((&vv.x)[r]);
                    ffma2(aL[r], vr, ab.x); ffma2(aH[r], vr, ab.y);
                }
            }
            #pragma unroll
            for (int r = 0; r < 4; r++)
                *(ulonglong2*)(sG + (i0 + r) * 36 + c4) = make_ulonglong2(aL[r], aH[r]);
        } else if (tid >= 96) {
            const int r = tid - 96;
            float acc = sc2[r];
            #pragma unroll
            for (int j4 = 0; j4 < 8; j4++) {
                const float4 cr = *(const float4*)(sC + r * 36 + j4 * 4);
                const float4 zz = *(const float4*)(szref + j4 * 4);
                acc -= cr.x * zz.x + cr.y * zz.y + cr.z * zz.z + cr.w * zz.w;
            }
            #pragma unroll
            for (int j = 0; j < 24; j++) acc += sAB[j * 36 + r] * sv[j];
            sQ[r] = acc;
        }
        __syncthreads();

        // ---- stage B: H tri = C + [A|B]^T G (+REG diag) (36 thr, 4x4, f32x2)
        if (tid < 36) {
            const int r0 = b_bi * 4, k0 = b_bk * 4;
            ull aL[4], aH[4];
            #pragma unroll
            for (int r = 0; r < 4; r++) {
                const ulonglong2 c2 = *(const ulonglong2*)(sC + (r0 + r) * 36 + k0);
                aL[r] = c2.x; aH[r] = c2.y;
            }
            #pragma unroll
            for (int j = 0; j < 24; j++) {
                const float4 aa = *(const float4*)(sAB + j * 36 + r0);  // AB[j][r0..r0+3]
                const ulonglong2 gg = *(const ulonglong2*)(sG + j * 36 + k0);
                #pragma unroll
                for (int r = 0; r < 4; r++) {
                    const ull ar = pack2((&aa.x)[r]);
                    ffma2(aL[r], ar, gg.x); ffma2(aH[r], ar, gg.y);
                }
            }
            #pragma unroll
            for (int r = 0; r < 4; r++) {
                float2 lo = unpack2(aL[r]), hi = unpack2(aH[r]);
                const int gr = r0 + r;
                if (gr >= 24) {
                    float v[4] = { lo.x, lo.y, hi.x, hi.y };
                    const int d = gr - k0;
                    if (d >= 0 && d < 4) v[d] += REGU;
                    *(float4*)(sH + gr * 36 + k0) = make_float4(v[0], v[1], v[2], v[3]);
                } else {
                    *(float4*)(sH + gr * 36 + k0) = make_float4(lo.x, lo.y, hi.x, hi.y);
                }
            }
        }
        __syncthreads();

        // ---- stage C: warp0 augmented GJ on [Quu | Qux | Qu] -> K, kv
        //      warps 1-3: commit prefetched tile
        if (tid < 32) {
            const int seg = tid >> 3, r = tid & 7;
            float m[9];
            if (seg == 0) {
                #pragma unroll
                for (int j = 0; j < 8; j++)
                    m[j] = (j <= r) ? sH[(24 + r) * 36 + 24 + j]
                                    : sH[(24 + j) * 36 + 24 + r];
                m[8] = sQ[24 + r];
            } else {
                const int cb = (seg - 1) * 8;
                #pragma unroll
                for (int j = 0; j < 8; j++)
                    m[j] = sH[(24 + r) * 36 + cb + j];
                m[8] = 0.f;
            }
            #pragma unroll
            for (int cc = 0; cc < 8; cc++) {
                const float p   = __shfl_sync(0xffffffffu, m[cc], cc);
                const float inv = __fdividef(1.0f, p);
                const float f   = __shfl_sync(0xffffffffu, m[cc], r);
                const float fi  = f * inv;
                const int src = (seg << 3) | cc;
                float pr[9];
                #pragma unroll
                for (int j = 0; j < 9; j++) pr[j] = __shfl_sync(0xffffffffu, m[j], src);
                const bool isPiv = (r == cc);
                #pragma unroll
                for (int j = 0; j < 9; j++)
                    m[j] = isPiv ? (m[j] * inv) : (m[j] - fi * pr[j]);
            }
            if (seg == 0) {
                skv[r] = -m[8];
                g_kv[(size_t)(b * T_HOR + t) * 8 + r] = -m[8];
            } else {
                const int cb = (seg - 1) * 8;
                const float4 k0v = make_float4(-m[0], -m[1], -m[2], -m[3]);
                const float4 k1v = make_float4(-m[4], -m[5], -m[6], -m[7]);
                *(float4*)(sK + r * 28 + cb)     = k0v;
                *(float4*)(sK + r * 28 + cb + 4) = k1v;
                float* gk = g_K + (size_t)(b * T_HOR + t) * 192 + r * 24 + cb;
                *(float4*)gk       = k0v;
                *(float4*)(gk + 4) = k1v;
            }
        } else if (t > 0) {
            const int idx = tid - 32;
            *(float4*)(sC + (idx >> 3) * 36 + ((idx & 7) << 2)) = pc0;
            {
                const int s = idx + 96;
                *(float4*)(sC + (s >> 3) * 36 + ((s & 7) << 2)) = pc1;
            }
            if (tid < 96) {
                const int s = idx + 192;
                *(float4*)(sC + (s >> 3) * 36 + ((s & 7) << 2)) = pc2;
            }
            if (tid < 64) sc2[tid - 32] = psc;
            else if (tid < 88) szref[tid - 64] = psc;
            else if (tid < 96) szref[24 + tid - 88] = psc;
        }
        __syncthreads();

        // ---- stage E: V = H + Qux^T K on lower tri, mirrored (42 thr, f32x2) ; vn (24 thr)
        if (tid < 42) {
            const int i0 = 4 * e_ti, k0 = 4 * e_tk;
            const int rh = i0 + (tid & 1) * 2;
            ull sL0 = 0, sH0 = 0, sL1 = 0, sH1 = 0;
            #pragma unroll
            for (int a = 0; a < 8; a++) {
                const float2 hi = *(const float2*)(sH + (24 + a) * 36 + rh);  // Qux[a][rh..rh+1]
                const ulonglong2 kk = *(const ulonglong2*)(sK + a * 28 + k0); // K[a][k0..k0+3]
                const ull h0 = pack2(hi.x), h1 = pack2(hi.y);
                ffma2(sL0, h0, kk.x); ffma2(sH0, h0, kk.y);
                ffma2(sL1, h1, kk.x); ffma2(sH1, h1, kk.y);
            }
            const float2 s0a = unpack2(sL0), s0b = unpack2(sH0);
            const float2 s1a = unpack2(sL1), s1b = unpack2(sH1);
            const float S0[4] = { s0a.x, s0a.y, s0b.x, s0b.y };
            const float S1[4] = { s1a.x, s1a.y, s1b.x, s1b.y };
            const float4 h40 = *(const float4*)(sH + rh * 36 + k0);
            const float4 h41 = *(const float4*)(sH + (rh + 1) * 36 + k0);
            float v0[4], v1[4];
            #pragma unroll
            for (int c = 0; c < 4; c++) {
                v0[c] = (&h40.x)[c] + S0[c];
                v1[c] = (&h41.x)[c] + S1[c];
            }
            *(float4*)(sV + rh * 28 + k0)       = make_float4(v0[0], v0[1], v0[2], v0[3]);
            *(float4*)(sV + (rh + 1) * 28 + k0) = make_float4(v1[0], v1[1], v1[2], v1[3]);
            if (e_ti != e_tk) {
                #pragma unroll
                for (int c = 0; c < 4; c++) {
                    sV[(k0 + c) * 28 + rh]     = v0[c];
                    sV[(k0 + c) * 28 + rh + 1] = v1[c];
                }
            }
        } else if (tid >= 96 && tid < 120) {
            const int i = tid - 96;
            float acc = sQ[i];
            #pragma unroll
            for (int a = 0; a < 8; a++) acc += sH[(24 + a) * 36 + i] * skv[a];
            sv[i] = acc;
        }
        __syncthreads();
    }

    // ---------------- forward rollout ----------------
    float* ob = d_out + (size_t)b * 3224;
    if (tid < 24) {
        const float xi = d_x0[b * 24 + tid];
        sx[0][tid] = xi;
        ob[tid] = xi;
    }
    float kr0 = 0.f, kr1 = 0.f;
    if (tid < 96) {
        const float2 k2 = *(const float2*)(g_K + (size_t)b * T_HOR * 192 + 2 * tid);
        kr0 = k2.x; kr1 = k2.y;
    } else if (tid < 104) {
        kr0 = g_kv[(size_t)b * T_HOR * 8 + (tid - 96)];
    }
    __syncthreads();

    int cur = 0;
    for (int t = 0; t < T_HOR; t++) {
        if (tid < 96)
            *(float2*)(sK2 + 2 * tid) = make_float2(kr0, kr1);
        else if (tid < 104)
            skv[tid - 96] = kr0;
        __syncthreads();
        if (t < T_HOR - 1) {
            if (tid < 96) {
                const float2 k2 = *(const float2*)(g_K + (size_t)(b * T_HOR + t + 1) * 192 + 2 * tid);
                kr0 = k2.x; kr1 = k2.y;
            } else if (tid < 104) {
                kr0 = g_kv[(size_t)(b * T_HOR + t + 1) * 8 + (tid - 96)];
            }
        }
        {
            const int a = tid >> 4, l = tid & 15;
            float p = 0.f;
            if (l < 12)
                p = sK2[a * 24 + l] * sx[cur][l] + sK2[a * 24 + l + 12] * sx[cur][l + 12];
            p += __shfl_down_sync(0xffffffffu, p, 8, 16);
            p += __shfl_down_sync(0xffffffffu, p, 4, 16);
            p += __shfl_down_sync(0xffffffffu, p, 2, 16);
            p += __shfl_down_sync(0xffffffffu, p, 1, 16);
            if (l == 0) {
                const float u = p + skv[a];
                su[a] = u;
                ob[2424 + t * 8 + a] = u;
            }
        }
        __syncthreads();
        if (tid < 24) {
            float acc = 0.f;
            #pragma unroll
            for (int j = 0; j < 24; j++) acc += sAB[tid * 36 + j] * sx[cur][j];
            #pragma unroll
            for (int a = 0; a < 8; a++) acc += sAB[tid * 36 + 24 + a] * su[a];
            sx[1 - cur][tid] = acc;
            ob[(t + 1) * 24 + tid] = acc;
        }
        __syncthreads();
        cur = 1 - cur;
    }
}

extern "C" void kernel_launch(void* const* d_in, const int* in_sizes, int n_in,
                              void* d_out, int out_size)
{
    const float* x0   = (const float*)d_in[0];
    const float* C    = (const float*)d_in[1];
    const float* c    = (const float*)d_in[2];
    const float* Cf   = (const float*)d_in[3];
    const float* cf   = (const float*)d_in[4];
    const float* xref = (const float*)d_in[5];
    const float* uref = (const float*)d_in[6];
    const float* A    = (const float*)d_in[7];
    const float* B    = (const float*)d_in[8];

    lqr_kernel<<<B_BATCH, 128>>>(x0, C, c, Cf, cf, xref, uref, A, B, (float*)d_out);
}

// round 8
// speedup vs baseline: 1.0442x; 1.0442x over previous
#include <cuda_runtime.h>

#define T_HOR 100
#define B_BATCH 512
#define REGU 1e-6f

typedef unsigned long long ull;

__device__ float g_K[B_BATCH * T_HOR * 8 * 24];
__device__ float g_kv[B_BATCH * T_HOR * 8];

__device__ __forceinline__ ull pack2(float s) {
    ull d; asm("mov.b64 %0, {%1, %1};" : "=l"(d) : "f"(s)); return d;
}
__device__ __forceinline__ void ffma2(ull& d, ull a, ull b) {
    asm("fma.rn.f32x2 %0, %1, %2, %0;" : "+l"(d) : "l"(a), "l"(b));
}
__device__ __forceinline__ float2 unpack2(ull v) {
    float2 r; asm("mov.b64 {%0, %1}, %2;" : "=f"(r.x), "=f"(r.y) : "l"(v)); return r;
}
__device__ __forceinline__ void cp16(unsigned sa, const void* g) {
    asm volatile("cp.async.cg.shared.global [%0], [%1], 16;" :: "r"(sa), "l"(g));
}
__device__ __forceinline__ void cp4(unsigned sa, const void* g) {
    asm volatile("cp.async.ca.shared.global [%0], [%1], 4;" :: "r"(sa), "l"(g));
}

extern "C" __global__ void __launch_bounds__(128, 4)
lqr_kernel(const float* __restrict__ d_x0,
           const float* __restrict__ d_C,
           const float* __restrict__ d_c,
           const float* __restrict__ d_Cf,
           const float* __restrict__ d_cf,
           const float* __restrict__ d_xref,
           const float* __restrict__ d_uref,
           const float* __restrict__ d_A,
           const float* __restrict__ d_B,
           float* __restrict__ d_out)
{
    __shared__ __align__(16) float sAB[24 * 36];
    __shared__ __align__(16) float sV[24 * 28];
    __shared__ __align__(16) float sC[2][32 * 36];
    __shared__ __align__(16) float sSc[2][64];     // [0..31]=c, [32..55]=xref, [56..63]=uref
    __shared__ __align__(16) float sG[24 * 36];
    __shared__ __align__(16) float sH[32 * 36];
    __shared__ __align__(16) float sK[8 * 28];
    __shared__ __align__(16) float sK2[192];
    __shared__ __align__(16) float sQ[32], sv[32];
    __shared__ float skv[8], su[8];
    __shared__ float sx[2][24];

    const int tid = threadIdx.x;
    const int b = blockIdx.x;

    // triangle tile maps (from tid>>1)
    int e_ti = 0, e_tk = 0;      // 6x6 lower tri (21 tiles) for V, 2 thr/tile
    int b_bi = 0, b_bk = 0;      // 8x8 lower tri (36 tiles) for H, 2 thr/tile
    {
        const int tt = tid >> 1;
        int s = 0;
        #pragma unroll
        for (int i = 0; i < 6; i++) {
            if (tt >= s && tt < s + i + 1) { e_ti = i; e_tk = tt - s; }
            s += i + 1;
        }
        s = 0;
        #pragma unroll
        for (int i = 0; i < 8; i++) {
            if (tt >= s && tt < s + i + 1) { b_bi = i; b_bk = tt - s; }
            s += i + 1;
        }
    }

    // ---------------- preamble ----------------
    for (int e = tid; e < 24 * 32; e += 128) {
        int j = e >> 5, cc = e & 31;
        sAB[j * 36 + cc] = (cc < 24) ? d_A[j * 24 + cc] : d_B[j * 8 + (cc - 24)];
    }
    for (int e = tid; e < 576; e += 128) {
        int i = e / 24, j = e - i * 24;
        sV[i * 28 + j] = d_Cf[(size_t)b * 1024 + i * 32 + j];
    }
    if (tid < 24) sQ[tid] = d_xref[((size_t)b * 101 + 100) * 24 + tid];
    {
        const float4* C4 = (const float4*)(d_C + ((size_t)b * T_HOR + 99) * 1024);
        #pragma unroll
        for (int ss = 0; ss < 2; ss++) {
            const int s = tid + ss * 128;
            *(float4*)(sC[0] + (s >> 3) * 36 + ((s & 7) << 2)) = C4[s];
        }
        if (tid < 32)
            sSc[0][tid] = d_c[((size_t)b * T_HOR + 99) * 32 + tid];
        else if (tid < 56)
            sSc[0][tid] = d_xref[((size_t)b * 101 + 99) * 24 + (tid - 32)];
        else if (tid < 64)
            sSc[0][tid] = d_uref[((size_t)b * T_HOR + 99) * 8 + (tid - 56)];
    }
    __syncthreads();
    if (tid < 24) {
        float acc = d_cf[b * 32 + tid];
        #pragma unroll
        for (int j = 0; j < 24; j++) acc -= sV[tid * 28 + j] * sQ[j];
        sv[tid] = acc;
    }
    __syncthreads();

    // ---------------- backward Riccati ----------------
    int buf = 0;
    for (int t = 99; t >= 0; --t) {
        const float* sCb  = sC[buf];
        const float* sScb = sSc[buf];

        // async prefetch of t-1 into the other buffers (no registers held)
        if (t > 0) {
            const float4* src = (const float4*)(d_C + ((size_t)b * T_HOR + t - 1) * 1024);
            float* dst = sC[buf ^ 1];
            #pragma unroll
            for (int ss = 0; ss < 2; ss++) {
                const int s = tid + ss * 128;
                cp16((unsigned)__cvta_generic_to_shared(dst + (s >> 3) * 36 + ((s & 7) << 2)),
                     src + s);
            }
            if (tid < 64) {
                const float* g;
                if (tid < 32)      g = d_c    + ((size_t)b * T_HOR + t - 1) * 32 + tid;
                else if (tid < 56) g = d_xref + ((size_t)b * 101 + t - 1) * 24 + (tid - 32);
                else               g = d_uref + ((size_t)b * T_HOR + t - 1) * 8 + (tid - 56);
                cp4((unsigned)__cvta_generic_to_shared(&sSc[buf ^ 1][tid]), g);
            }
            asm volatile("cp.async.commit_group;");
        }

        // ---- stage A: G = V*[A|B] (96 thr, 2x4, f32x2) ; Q = [Qx|Qu] (32 thr)
        if (tid < 96) {
            const int i0 = (tid >> 3) * 2, c4 = (tid & 7) << 2;
            ull aL0 = 0, aH0 = 0, aL1 = 0, aH1 = 0;
            #pragma unroll
            for (int j = 0; j < 24; j++) {
                const float2 vv = *(const float2*)(sV + j * 28 + i0);
                const ulonglong2 ab = *(const ulonglong2*)(sAB + j * 36 + c4);
                const ull v0 = pack2(vv.x), v1 = pack2(vv.y);
                ffma2(aL0, v0, ab.x); ffma2(aH0, v0, ab.y);
                ffma2(aL1, v1, ab.x); ffma2(aH1, v1, ab.y);
            }
            *(ulonglong2*)(sG + i0 * 36 + c4)       = make_ulonglong2(aL0, aH0);
            *(ulonglong2*)(sG + (i0 + 1) * 36 + c4) = make_ulonglong2(aL1, aH1);
        } else {
            const int r = tid - 96;
            float acc = sScb[r];
            #pragma unroll
            for (int j4 = 0; j4 < 8; j4++) {
                const float4 cr = *(const float4*)(sCb + r * 36 + j4 * 4);
                const float4 zz = *(const float4*)(sScb + 32 + j4 * 4);
                acc -= cr.x * zz.x + cr.y * zz.y + cr.z * zz.z + cr.w * zz.w;
            }
            #pragma unroll
            for (int j = 0; j < 24; j++) acc += sAB[j * 36 + r] * sv[j];
            sQ[r] = acc;
        }
        __syncthreads();

        // ---- stage B: H tri = C + [A|B]^T G (+REG diag) (72 thr, 2x4, f32x2)
        if (tid < 72) {
            const int r0 = b_bi * 4 + (tid & 1) * 2;
            const int k0 = b_bk * 4;
            const ulonglong2 c0 = *(const ulonglong2*)(sCb + r0 * 36 + k0);
            const ulonglong2 c1 = *(const ulonglong2*)(sCb + (r0 + 1) * 36 + k0);
            ull aL0 = c0.x, aH0 = c0.y, aL1 = c1.x, aH1 = c1.y;
            #pragma unroll
            for (int j = 0; j < 24; j++) {
                const float2 aa = *(const float2*)(sAB + j * 36 + r0);
                const ulonglong2 gg = *(const ulonglong2*)(sG + j * 36 + k0);
                const ull a0 = pack2(aa.x), a1 = pack2(aa.y);
                ffma2(aL0, a0, gg.x); ffma2(aH0, a0, gg.y);
                ffma2(aL1, a1, gg.x); ffma2(aH1, a1, gg.y);
            }
            float2 r0lo = unpack2(aL0), r0hi = unpack2(aH0);
            float2 r1lo = unpack2(aL1), r1hi = unpack2(aH1);
            if (r0 >= 24) {
                float v0[4] = { r0lo.x, r0lo.y, r0hi.x, r0hi.y };
                float v1[4] = { r1lo.x, r1lo.y, r1hi.x, r1hi.y };
                const int d0 = r0 - k0;
                if (d0 >= 0 && d0 < 4) v0[d0] += REGU;
                const int d1 = r0 + 1 - k0;
                if (d1 >= 0 && d1 < 4) v1[d1] += REGU;
                *(float4*)(sH + r0 * 36 + k0)       = make_float4(v0[0], v0[1], v0[2], v0[3]);
                *(float4*)(sH + (r0 + 1) * 36 + k0) = make_float4(v1[0], v1[1], v1[2], v1[3]);
            } else {
                *(float4*)(sH + r0 * 36 + k0)       = make_float4(r0lo.x, r0lo.y, r0hi.x, r0hi.y);
                *(float4*)(sH + (r0 + 1) * 36 + k0) = make_float4(r1lo.x, r1lo.y, r1hi.x, r1hi.y);
            }
        }
        __syncthreads();

        // ---- stage C: warp0 augmented GJ on [Quu | Qux | Qu] -> K, kv
        if (tid < 32) {
            const int seg = tid >> 3, r = tid & 7;
            float m[9];
            if (seg == 0) {
                #pragma unroll
                for (int j = 0; j < 8; j++)
                    m[j] = (j <= r) ? sH[(24 + r) * 36 + 24 + j]
                                    : sH[(24 + j) * 36 + 24 + r];
                m[8] = sQ[24 + r];
            } else {
                const int cb = (seg - 1) * 8;
                #pragma unroll
                for (int j = 0; j < 8; j++)
                    m[j] = sH[(24 + r) * 36 + cb + j];
                m[8] = 0.f;
            }
            #pragma unroll
            for (int cc = 0; cc < 8; cc++) {
                const float p   = __shfl_sync(0xffffffffu, m[cc], cc);
                const float inv = __fdividef(1.0f, p);
                const float f   = __shfl_sync(0xffffffffu, m[cc], r);
                const float fi  = f * inv;
                const int src = (seg << 3) | cc;
                float pr[9];
                #pragma unroll
                for (int j = 0; j < 9; j++) pr[j] = __shfl_sync(0xffffffffu, m[j], src);
                const bool isPiv = (r == cc);
                #pragma unroll
                for (int j = 0; j < 9; j++)
                    m[j] = isPiv ? (m[j] * inv) : (m[j] - fi * pr[j]);
            }
            if (seg == 0) {
                skv[r] = -m[8];
                g_kv[(size_t)(b * T_HOR + t) * 8 + r] = -m[8];
            } else {
                const int cb = (seg - 1) * 8;
                const float4 k0v = make_float4(-m[0], -m[1], -m[2], -m[3]);
                const float4 k1v = make_float4(-m[4], -m[5], -m[6], -m[7]);
                *(float4*)(sK + r * 28 + cb)     = k0v;
                *(float4*)(sK + r * 28 + cb + 4) = k1v;
                float* gk = g_K + (size_t)(b * T_HOR + t) * 192 + r * 24 + cb;
                *(float4*)gk       = k0v;
                *(float4*)(gk + 4) = k1v;
            }
        }
        __syncthreads();

        // ---- stage E: V = H + Qux^T K on lower tri, mirrored (42 thr, f32x2) ; vn (24 thr)
        if (tid < 42) {
            const int i0 = 4 * e_ti, k0 = 4 * e_tk;
            const int rh = i0 + (tid & 1) * 2;
            ull sL0 = 0, sH0 = 0, sL1 = 0, sH1 = 0;
            #pragma unroll
            for (int a = 0; a < 8; a++) {
                const float2 hi = *(const float2*)(sH + (24 + a) * 36 + rh);
                const ulonglong2 kk = *(const ulonglong2*)(sK + a * 28 + k0);
                const ull h0 = pack2(hi.x), h1 = pack2(hi.y);
                ffma2(sL0, h0, kk.x); ffma2(sH0, h0, kk.y);
                ffma2(sL1, h1, kk.x); ffma2(sH1, h1, kk.y);
            }
            const float2 s0a = unpack2(sL0), s0b = unpack2(sH0);
            const float2 s1a = unpack2(sL1), s1b = unpack2(sH1);
            const float S0[4] = { s0a.x, s0a.y, s0b.x, s0b.y };
            const float S1[4] = { s1a.x, s1a.y, s1b.x, s1b.y };
            const float4 h40 = *(const float4*)(sH + rh * 36 + k0);
            const float4 h41 = *(const float4*)(sH + (rh + 1) * 36 + k0);
            float v0[4], v1[4];
            #pragma unroll
            for (int c = 0; c < 4; c++) {
                v0[c] = (&h40.x)[c] + S0[c];
                v1[c] = (&h41.x)[c] + S1[c];
            }
            *(float4*)(sV + rh * 28 + k0)       = make_float4(v0[0], v0[1], v0[2], v0[3]);
            *(float4*)(sV + (rh + 1) * 28 + k0) = make_float4(v1[0], v1[1], v1[2], v1[3]);
            if (e_ti != e_tk) {
                #pragma unroll
                for (int c = 0; c < 4; c++) {
                    sV[(k0 + c) * 28 + rh]     = v0[c];
                    sV[(k0 + c) * 28 + rh + 1] = v1[c];
                }
            }
        } else if (tid >= 96 && tid < 120) {
            const int i = tid - 96;
            float acc = sQ[i];
            #pragma unroll
            for (int a = 0; a < 8; a++) acc += sH[(24 + a) * 36 + i] * skv[a];
            sv[i] = acc;
        }
        if (t > 0) asm volatile("cp.async.wait_group 0;" ::: "memory");
        __syncthreads();
        buf ^= 1;
    }

    // ---------------- forward rollout ----------------
    float* ob = d_out + (size_t)b * 3224;
    if (tid < 24) {
        const float xi = d_x0[b * 24 + tid];
        sx[0][tid] = xi;
        ob[tid] = xi;
    }
    float kr0 = 0.f, kr1 = 0.f;
    if (tid < 96) {
        const float2 k2 = *(const float2*)(g_K + (size_t)b * T_HOR * 192 + 2 * tid);
        kr0 = k2.x; kr1 = k2.y;
    } else if (tid < 104) {
        kr0 = g_kv[(size_t)b * T_HOR * 8 + (tid - 96)];
    }
    __syncthreads();

    int cur = 0;
    for (int t = 0; t < T_HOR; t++) {
        if (tid < 96)
            *(float2*)(sK2 + 2 * tid) = make_float2(kr0, kr1);
        else if (tid < 104)
            skv[tid - 96] = kr0;
        __syncthreads();
        if (t < T_HOR - 1) {
            if (tid < 96) {
                const float2 k2 = *(const float2*)(g_K + (size_t)(b * T_HOR + t + 1) * 192 + 2 * tid);
                kr0 = k2.x; kr1 = k2.y;
            } else if (tid < 104) {
                kr0 = g_kv[(size_t)(b * T_HOR + t + 1) * 8 + (tid - 96)];
            }
        }
        {
            const int a = tid >> 4, l = tid & 15;
            float p = 0.f;
            if (l < 12)
                p = sK2[a * 24 + l] * sx[cur][l] + sK2[a * 24 + l + 12] * sx[cur][l + 12];
            p += __shfl_down_sync(0xffffffffu, p, 8, 16);
            p += __shfl_down_sync(0xffffffffu, p, 4, 16);
            p += __shfl_down_sync(0xffffffffu, p, 2, 16);
            p += __shfl_down_sync(0xffffffffu, p, 1, 16);
            if (l == 0) {
                const float u = p + skv[a];
                su[a] = u;
                ob[2424 + t * 8 + a] = u;
            }
        }
        __syncthreads();
        if (tid < 24) {
            float acc = 0.f;
            #pragma unroll
            for (int j = 0; j < 24; j++) acc += sAB[tid * 36 + j] * sx[cur][j];
            #pragma unroll
            for (int a = 0; a < 8; a++) acc += sAB[tid * 36 + 24 + a] * su[a];
            sx[1 - cur][tid] = acc;
            ob[(t + 1) * 24 + tid] = acc;
        }
        __syncthreads();
        cur = 1 - cur;
    }
}

extern "C" void kernel_launch(void* const* d_in, const int* in_sizes, int n_in,
                              void* d_out, int out_size)
{
    const float* x0   = (const float*)d_in[0];
    const float* C    = (const float*)d_in[1];
    const float* c    = (const float*)d_in[2];
    const float* Cf   = (const float*)d_in[3];
    const float* cf   = (const float*)d_in[4];
    const float* xref = (const float*)d_in[5];
    const float* uref = (const float*)d_in[6];
    const float* A    = (const float*)d_in[7];
    const float* B    = (const float*)d_in[8];

    lqr_kernel<<<B_BATCH, 128>>>(x0, C, c, Cf, cf, xref, uref, A, B, (float*)d_out);
}